// round 1
// baseline (speedup 1.0000x reference)
#include <cuda_runtime.h>
#include <cuda_bf16.h>
#include <math.h>
#include <float.h>
#include <stdint.h>

#define BATCH 4
#define NPTS 4096
#define KNN 16
#define CIN 9
#define CH 128
#define NCLS 13

// ---------------- scratch pool (device globals: allocation-guard safe) ------
// offsets in floats
#define OFF_XIN   0                        // 4*4096*9      = 147456
#define OFF_IDX   (OFF_XIN  + 147456)      // 4*4096*16     = 262144 (ints)
#define OFF_E1    (OFF_IDX  + 262144)      // 4*4096*128    = 2097152
#define OFF_XCUR  (OFF_E1   + 2097152)
#define OFF_Q     (OFF_XCUR + 2097152)
#define OFF_K     (OFF_Q    + 2097152)
#define OFF_V     (OFF_K    + 2097152)
#define OFF_XCAT  (OFF_V    + 2097152)     // 4*4096*384    = 6291456
#define OFF_FUSE  (OFF_XCAT + 6291456)     // 4*4096*1024   = 16777216
#define OFF_G     (OFF_FUSE + 16777216)    // 4*2048        = 8192
#define OFF_BEFF  (OFF_G    + 8192)        // 4*512         = 2048
#define OFF_C1    (OFF_BEFF + 2048)        // 4*4096*512    = 8388608
#define OFF_C2    (OFF_C1   + 8388608)     // 4*4096*256    = 4194304
#define POOL_SZ   (OFF_C2   + 4194304)

__device__ __align__(16) float g_pool[POOL_SZ];

// ---------------- transpose inputs (b,c,n) -> (p, c) ------------------------
__global__ void tin_kernel(const float* __restrict__ in, float* __restrict__ xin) {
    int p = blockIdx.x * blockDim.x + threadIdx.x;
    if (p >= BATCH * NPTS) return;
    int b = p / NPTS, n = p % NPTS;
    #pragma unroll
    for (int c = 0; c < CIN; c++)
        xin[(size_t)p * CIN + c] = in[((size_t)b * CIN + c) * NPTS + n];
}

// ---------------- KNN: one block (256 thr) per query point ------------------
__global__ void knn_kernel(const float* __restrict__ in, int* __restrict__ idxo) {
    int p = blockIdx.x;
    int b = p / NPTS, n = p % NPTS;
    const float* xb = in + (size_t)b * CIN * NPTS;
    __shared__ float sd[NPTS];
    __shared__ float rmin[256];
    __shared__ int   rmi[256];
    float x0 = xb[n], y0 = xb[NPTS + n], z0 = xb[2 * NPTS + n];
    float sq0 = x0 * x0 + y0 * y0 + z0 * z0;
    for (int m = threadIdx.x; m < NPTS; m += 256) {
        float xm = xb[m], ym = xb[NPTS + m], zm = xb[2 * NPTS + m];
        float sqm = xm * xm + ym * ym + zm * zm;
        float dot = x0 * xm + y0 * ym + z0 * zm;
        sd[m] = sq0 + sqm - 2.0f * dot;
    }
    __syncthreads();
    for (int t = 0; t < KNN; t++) {
        float best = FLT_MAX; int bi = 0x7fffffff;
        for (int m = threadIdx.x; m < NPTS; m += 256) {
            float dm = sd[m];
            if (dm < best) { best = dm; bi = m; }
        }
        rmin[threadIdx.x] = best; rmi[threadIdx.x] = bi;
        __syncthreads();
        for (int st = 128; st > 0; st >>= 1) {
            if (threadIdx.x < st) {
                float o = rmin[threadIdx.x + st]; int oi = rmi[threadIdx.x + st];
                if (o < rmin[threadIdx.x] ||
                    (o == rmin[threadIdx.x] && oi < rmi[threadIdx.x])) {
                    rmin[threadIdx.x] = o; rmi[threadIdx.x] = oi;
                }
            }
            __syncthreads();
        }
        if (threadIdx.x == 0) {
            idxo[(size_t)p * KNN + t] = rmi[0];
            sd[rmi[0]] = FLT_MAX;
        }
        __syncthreads();
    }
}

// ---------------- generic tiled fp32 GEMM + epilogue ------------------------
// out[b][n][o] = act( s[o]*(acc + b1[o] + addb[b*Od+o]) + sh[o] )
// X: [b][n][k] (k contiguous), W: [o][ldw] (k contiguous)
// act: 0 none, 1 relu, 2 leaky 0.2 ; transOut: out[b][o][n]
__global__ void gemm_epi_kernel(const float* __restrict__ X, const float* __restrict__ W,
                                int ldw, const float* __restrict__ b1,
                                const float* __restrict__ addb,
                                const float* __restrict__ s, const float* __restrict__ sh,
                                float* __restrict__ out, int Np, int Kd, int Od,
                                int act, int transOut) {
    int b  = blockIdx.z;
    int n0 = blockIdx.x * 64;
    int o0 = blockIdx.y * 64;
    const float* Xb = X + (size_t)b * Np * Kd;
    __shared__ float As[16][64];
    __shared__ float Ws[16][64];
    int tid = threadIdx.x;
    int tx = tid & 15, ty = tid >> 4;
    float acc[4][4] = {};
    for (int k0 = 0; k0 < Kd; k0 += 16) {
        for (int l = tid; l < 64 * 16; l += 256) {
            int nn = l >> 4, kk = l & 15;
            int n = n0 + nn, k = k0 + kk;
            As[kk][nn] = (n < Np && k < Kd) ? Xb[(size_t)n * Kd + k] : 0.f;
        }
        for (int l = tid; l < 64 * 16; l += 256) {
            int oo = l >> 4, kk = l & 15;
            int o = o0 + oo, k = k0 + kk;
            Ws[kk][oo] = (o < Od && k < Kd) ? W[(size_t)o * ldw + k] : 0.f;
        }
        __syncthreads();
        #pragma unroll
        for (int kk = 0; kk < 16; kk++) {
            float a[4], w[4];
            *(float4*)a = *(const float4*)&As[kk][ty * 4];
            *(float4*)w = *(const float4*)&Ws[kk][tx * 4];
            #pragma unroll
            for (int i = 0; i < 4; i++)
                #pragma unroll
                for (int j = 0; j < 4; j++)
                    acc[i][j] = fmaf(a[i], w[j], acc[i][j]);
        }
        __syncthreads();
    }
    #pragma unroll
    for (int i = 0; i < 4; i++) {
        int n = n0 + ty * 4 + i;
        if (n >= Np) continue;
        #pragma unroll
        for (int j = 0; j < 4; j++) {
            int o = o0 + tx * 4 + j;
            if (o >= Od) continue;
            float y = acc[i][j];
            float pre = y + (b1 ? b1[o] : 0.f) + (addb ? addb[b * Od + o] : 0.f);
            float z = (s ? s[o] : 1.f) * pre + (sh ? sh[o] : 0.f);
            if (act == 1) z = fmaxf(z, 0.f);
            else if (act == 2) z = (z > 0.f) ? z : 0.2f * z;
            if (transOut) out[((size_t)b * Od + o) * Np + n] = z;
            else          out[((size_t)b * Np + n) * Od + o] = z;
        }
    }
}

// ---------------- attention block: one 128-thread block per point -----------
__global__ void attn_kernel(const float* __restrict__ q, const float* __restrict__ kbuf,
                            const float* __restrict__ vbuf, const int* __restrict__ idx,
                            const float* __restrict__ in, const float* __restrict__ wpos,
                            const float* __restrict__ wo, const float* __restrict__ sv,
                            const float* __restrict__ bv, float* __restrict__ xcur,
                            float* __restrict__ xcat, int blk) {
    int p = blockIdx.x;
    int b = p >> 12, n = p & (NPTS - 1);
    int tid = threadIdx.x;
    __shared__ float qs[CH], aggs[CH], attn[KNN], slog[KNN], rel[KNN][3];
    __shared__ int sIdx[KNN];
    qs[tid] = q[(size_t)p * CH + tid];
    if (tid < KNN) sIdx[tid] = idx[(size_t)p * KNN + tid];
    __syncthreads();
    const float* xb = in + (size_t)b * CIN * NPTS;
    int w = tid >> 5, lane = tid & 31;
    for (int kk = w; kk < KNN; kk += 4) {
        int m = sIdx[kk];
        const float* kr = kbuf + ((size_t)b * NPTS + m) * CH;
        float d = 0.f;
        #pragma unroll
        for (int c = lane; c < CH; c += 32) d = fmaf(qs[c], kr[c], d);
        #pragma unroll
        for (int st = 16; st > 0; st >>= 1) d += __shfl_down_sync(0xffffffffu, d, st);
        if (lane == 0) slog[kk] = d * 0.08838834764831845f; // 1/sqrt(128)
        if (lane < 3)  rel[kk][lane] = xb[lane * NPTS + n] - xb[lane * NPTS + m];
    }
    __syncthreads();
    if (tid == 0) {
        float mx = slog[0];
        #pragma unroll
        for (int i = 1; i < KNN; i++) mx = fmaxf(mx, slog[i]);
        float sum = 0.f;
        #pragma unroll
        for (int i = 0; i < KNN; i++) { float e = expf(slog[i] - mx); attn[i] = e; sum += e; }
        float inv = 1.f / sum;
        #pragma unroll
        for (int i = 0; i < KNN; i++) attn[i] *= inv;
    }
    __syncthreads();
    float w0 = wpos[tid * 3 + 0], w1 = wpos[tid * 3 + 1], w2 = wpos[tid * 3 + 2];
    float acc = 0.f;
    #pragma unroll
    for (int kk = 0; kk < KNN; kk++) {
        int m = sIdx[kk];
        float vn = vbuf[((size_t)b * NPTS + m) * CH + tid]
                 + w0 * rel[kk][0] + w1 * rel[kk][1] + w2 * rel[kk][2];
        acc = fmaf(attn[kk], vn, acc);
    }
    aggs[tid] = acc;
    __syncthreads();
    float y = 0.f;
    const float* wr = wo + (size_t)tid * CH;
    #pragma unroll 8
    for (int c = 0; c < CH; c++) y = fmaf(wr[c], aggs[c], y);
    float z = fmaxf(sv[tid] * y + bv[tid], 0.f);
    float xn = xcur[(size_t)p * CH + tid] + z;
    xcur[(size_t)p * CH + tid] = xn;
    xcat[(size_t)p * (3 * CH) + blk * CH + tid] = xn;
}

// ---------------- global max/mean pool over n -------------------------------
__global__ void pool_kernel(const float* __restrict__ fuse, float* __restrict__ g) {
    int b = blockIdx.y;
    int ch = blockIdx.x * 32 + (threadIdx.x & 31);
    int r = threadIdx.x >> 5;
    float mx = -FLT_MAX, sm = 0.f;
    for (int n = r; n < NPTS; n += 8) {
        float v = fuse[((size_t)b * NPTS + n) * 1024 + ch];
        mx = fmaxf(mx, v); sm += v;
    }
    __shared__ float smx[256], ssm[256];
    smx[threadIdx.x] = mx; ssm[threadIdx.x] = sm;
    __syncthreads();
    for (int st = 128; st >= 32; st >>= 1) {
        if (threadIdx.x < st) {
            smx[threadIdx.x] = fmaxf(smx[threadIdx.x], smx[threadIdx.x + st]);
            ssm[threadIdx.x] += ssm[threadIdx.x + st];
        }
        __syncthreads();
    }
    if (r == 0) {
        g[b * 2048 + ch] = smx[threadIdx.x];
        g[b * 2048 + 1024 + ch] = ssm[threadIdx.x] * (1.f / 4096.f);
    }
}

// ------- fold global features into per-(b,o) cls1 bias ----------------------
__global__ void beff_kernel(const float* __restrict__ w1, const float* __restrict__ bias1,
                            const float* __restrict__ g, float* __restrict__ beff) {
    int o = blockIdx.x * blockDim.x + threadIdx.x;
    int b = blockIdx.y;
    if (o >= 512) return;
    const float* wr = w1 + (size_t)o * 3072 + 1024;
    const float* gb = g + b * 2048;
    float acc = bias1[o];
    for (int j = 0; j < 2048; j++) acc = fmaf(wr[j], gb[j], acc);
    beff[b * 512 + o] = acc;
}

// ---------------- launcher --------------------------------------------------
extern "C" void kernel_launch(void* const* d_in, const int* in_sizes, int n_in,
                              void* d_out, int out_size) {
    const float* in_inputs  = (const float*)d_in[0];
    const float* emb_w1     = (const float*)d_in[1];
    const float* emb_s1     = (const float*)d_in[2];
    const float* emb_b1     = (const float*)d_in[3];
    const float* emb_w2     = (const float*)d_in[4];
    const float* emb_s2     = (const float*)d_in[5];
    const float* emb_b2     = (const float*)d_in[6];
    const float* blk_wq     = (const float*)d_in[7];
    const float* blk_wk     = (const float*)d_in[8];
    const float* blk_wv     = (const float*)d_in[9];
    const float* blk_wpos   = (const float*)d_in[10];
    const float* blk_wo     = (const float*)d_in[11];
    const float* blk_s      = (const float*)d_in[12];
    const float* blk_b      = (const float*)d_in[13];
    const float* fuse_w     = (const float*)d_in[14];
    const float* fuse_s     = (const float*)d_in[15];
    const float* fuse_b     = (const float*)d_in[16];
    const float* cls_w1     = (const float*)d_in[17];
    const float* cls_bias1  = (const float*)d_in[18];
    const float* cls_s1     = (const float*)d_in[19];
    const float* cls_sh1    = (const float*)d_in[20];
    const float* cls_w2     = (const float*)d_in[21];
    const float* cls_bias2  = (const float*)d_in[22];
    const float* cls_s2     = (const float*)d_in[23];
    const float* cls_sh2    = (const float*)d_in[24];
    const float* cls_w3     = (const float*)d_in[25];
    const float* cls_bias3  = (const float*)d_in[26];

    float* pool = nullptr;
    cudaGetSymbolAddress((void**)&pool, g_pool);
    float* xin  = pool + OFF_XIN;
    int*   idx  = (int*)(pool + OFF_IDX);
    float* e1   = pool + OFF_E1;
    float* xcur = pool + OFF_XCUR;
    float* qb   = pool + OFF_Q;
    float* kb   = pool + OFF_K;
    float* vb   = pool + OFF_V;
    float* xcat = pool + OFF_XCAT;
    float* fuse = pool + OFF_FUSE;
    float* g    = pool + OFF_G;
    float* beff = pool + OFF_BEFF;
    float* c1   = pool + OFF_C1;
    float* c2   = pool + OFF_C2;
    float* outp = (float*)d_out;

    const int P = BATCH * NPTS;

    tin_kernel<<<(P + 255) / 256, 256>>>(in_inputs, xin);
    knn_kernel<<<P, 256>>>(in_inputs, idx);

    dim3 gC(NPTS / 64, CH / 64, BATCH);
    // embedding
    gemm_epi_kernel<<<gC, 256>>>(xin, emb_w1, CIN, nullptr, nullptr, emb_s1, emb_b1,
                                 e1, NPTS, CIN, CH, 1, 0);
    gemm_epi_kernel<<<gC, 256>>>(e1, emb_w2, CH, nullptr, nullptr, emb_s2, emb_b2,
                                 xcur, NPTS, CH, CH, 1, 0);
    // attention blocks
    for (int i = 0; i < 3; i++) {
        const float* wq = blk_wq + (size_t)i * CH * CH;
        const float* wk = blk_wk + (size_t)i * CH * CH;
        const float* wv = blk_wv + (size_t)i * CH * CH;
        gemm_epi_kernel<<<gC, 256>>>(xcur, wq, CH, nullptr, nullptr, nullptr, nullptr,
                                     qb, NPTS, CH, CH, 0, 0);
        gemm_epi_kernel<<<gC, 256>>>(xcur, wk, CH, nullptr, nullptr, nullptr, nullptr,
                                     kb, NPTS, CH, CH, 0, 0);
        gemm_epi_kernel<<<gC, 256>>>(xcur, wv, CH, nullptr, nullptr, nullptr, nullptr,
                                     vb, NPTS, CH, CH, 0, 0);
        attn_kernel<<<P, CH>>>(qb, kb, vb, idx, in_inputs,
                               blk_wpos + (size_t)i * CH * 3,
                               blk_wo + (size_t)i * CH * CH,
                               blk_s + (size_t)i * CH, blk_b + (size_t)i * CH,
                               xcur, xcat, i);
    }
    // fuse 384 -> 1024 (leaky 0.2)
    dim3 gF(NPTS / 64, 1024 / 64, BATCH);
    gemm_epi_kernel<<<gF, 256>>>(xcat, fuse_w, 3 * CH, nullptr, nullptr, fuse_s, fuse_b,
                                 fuse, NPTS, 3 * CH, 1024, 2, 0);
    // global pool + fold into cls1 bias
    pool_kernel<<<dim3(32, BATCH), 256>>>(fuse, g);
    beff_kernel<<<dim3(2, BATCH), 256>>>(cls_w1, cls_bias1, g, beff);
    // classifier
    dim3 g1(NPTS / 64, 512 / 64, BATCH);
    gemm_epi_kernel<<<g1, 256>>>(fuse, cls_w1, 3072, nullptr, beff, cls_s1, cls_sh1,
                                 c1, NPTS, 1024, 512, 1, 0);
    dim3 g2(NPTS / 64, 256 / 64, BATCH);
    gemm_epi_kernel<<<g2, 256>>>(c1, cls_w2, 512, cls_bias2, nullptr, cls_s2, cls_sh2,
                                 c2, NPTS, 512, 256, 1, 0);
    dim3 g3(NPTS / 64, 1, BATCH);
    gemm_epi_kernel<<<g3, 256>>>(c2, cls_w3, 256, cls_bias3, nullptr, nullptr, nullptr,
                                 outp, NPTS, 256, NCLS, 0, 1);
}

// round 2
// speedup vs baseline: 1.8902x; 1.8902x over previous
#include <cuda_runtime.h>
#include <cuda_bf16.h>
#include <math.h>
#include <float.h>
#include <stdint.h>

#define BATCH 4
#define NPTS 4096
#define KNN 16
#define CIN 9
#define CH 128
#define NCLS 13

// ---------------- scratch pool (device globals: allocation-guard safe) ------
// offsets in floats
#define OFF_XIN   0                          // 4*4096*9
#define OFF_IDX   (OFF_XIN  + 147456)        // 4*4096*16 (ints)
#define OFF_E1    (OFF_IDX  + 262144)        // 4*4096*128
#define OFF_XCUR  (OFF_E1   + 2097152)       // 4*4096*128
#define OFF_QKV   (OFF_XCUR + 2097152)       // 4*4096*384
#define OFF_AGG   (OFF_QKV  + 6291456)       // 4*4096*128
#define OFF_XCAT  (OFF_AGG  + 2097152)       // 4*4096*384
#define OFF_FUSE  (OFF_XCAT + 6291456)       // 4*4096*1024
#define OFF_G     (OFF_FUSE + 16777216)      // 4*2048
#define OFF_BEFF  (OFF_G    + 8192)          // 4*512
#define OFF_C1    (OFF_BEFF + 2048)          // 4*4096*512
#define OFF_C2    (OFF_C1   + 8388608)       // 4*4096*256
#define OFF_WPK   (OFF_C2   + 4194304)       // 3*384*128
#define POOL_SZ   (OFF_WPK  + 147456)

__device__ __align__(16) float g_pool[POOL_SZ];

// ---------------- transpose inputs (b,c,n) -> (p, c) ------------------------
__global__ void tin_kernel(const float* __restrict__ in, float* __restrict__ xin) {
    int p = blockIdx.x * blockDim.x + threadIdx.x;
    if (p >= BATCH * NPTS) return;
    int b = p / NPTS, n = p % NPTS;
    #pragma unroll
    for (int c = 0; c < CIN; c++)
        xin[(size_t)p * CIN + c] = in[((size_t)b * CIN + c) * NPTS + n];
}

// ---------------- pack qkv weights: wp[i][o(0..383)][k] ---------------------
__global__ void pack_qkv_kernel(const float* __restrict__ wq, const float* __restrict__ wk,
                                const float* __restrict__ wv, float* __restrict__ wp) {
    int i = blockIdx.y;
    int t = blockIdx.x * 256 + threadIdx.x;
    if (t >= 384 * CH) return;
    int o = t / CH, k = t % CH;
    const float* src = (o < CH) ? wq : (o < 2 * CH) ? wk : wv;
    int oo = o & (CH - 1);
    wp[(size_t)i * 384 * CH + t] = src[(size_t)i * CH * CH + (size_t)oo * CH + k];
}

// ---------------- KNN: one warp per query point -----------------------------
__global__ void knn_warp_kernel(const float* __restrict__ in, int* __restrict__ idxo) {
    int gw = (blockIdx.x * blockDim.x + threadIdx.x) >> 5;
    int lane = threadIdx.x & 31;
    if (gw >= BATCH * NPTS) return;
    int b = gw >> 12, n = gw & (NPTS - 1);
    const float* xb = in + (size_t)b * CIN * NPTS;
    float x0 = xb[n], y0 = xb[NPTS + n], z0 = xb[2 * NPTS + n];
    float sq0 = x0 * x0 + y0 * y0 + z0 * z0;
    float dl[KNN]; int il[KNN];
    #pragma unroll
    for (int t = 0; t < KNN; t++) { dl[t] = FLT_MAX; il[t] = 0x7fffffff; }
    float worst = FLT_MAX;
    for (int i = 0; i < NPTS / 32; i++) {
        int m = i * 32 + lane;
        float xm = xb[m], ym = xb[NPTS + m], zm = xb[2 * NPTS + m];
        float sqm = xm * xm + ym * ym + zm * zm;
        float dot = x0 * xm + y0 * ym + z0 * zm;
        float dm = sq0 + sqm - 2.0f * dot;
        if (dm < worst) {
            bool done = false;
            #pragma unroll
            for (int t = 0; t < KNN; t++) {
                if (!done && dl[t] == worst) { dl[t] = dm; il[t] = m; done = true; }
            }
            worst = dl[0];
            #pragma unroll
            for (int t = 1; t < KNN; t++) worst = fmaxf(worst, dl[t]);
        }
    }
    int* op = idxo + (size_t)gw * KNN;
    for (int t = 0; t < KNN; t++) {
        float lm = dl[0]; int li = il[0];
        #pragma unroll
        for (int j = 1; j < KNN; j++) {
            if (dl[j] < lm || (dl[j] == lm && il[j] < li)) { lm = dl[j]; li = il[j]; }
        }
        float bm = lm; int bi = li;
        #pragma unroll
        for (int off = 16; off > 0; off >>= 1) {
            float om = __shfl_down_sync(0xffffffffu, bm, off);
            int   oi = __shfl_down_sync(0xffffffffu, bi, off);
            if (om < bm || (om == bm && oi < bi)) { bm = om; bi = oi; }
        }
        bm = __shfl_sync(0xffffffffu, bm, 0);
        bi = __shfl_sync(0xffffffffu, bi, 0);
        if (lane == 0) op[t] = bi;
        if (bi == li && bm == lm) {
            #pragma unroll
            for (int j = 0; j < KNN; j++) if (il[j] == bi) dl[j] = FLT_MAX;
        }
    }
}

// ---------------- 128x128x32 tiled fp32 GEMM + fused epilogue ---------------
// acc = X[b][n][:] . W[o][:]
// z = act( s[o]*(acc + b1[o] + addb[b*Od+o]) + sh[o] ) (+ resid)
// out[b][n*ldo+o] (or transposed), optional out2[b][n*ldo2+o]
__global__ __launch_bounds__(256, 2)
void gemm128_kernel(const float* __restrict__ X, const float* __restrict__ W,
                    int ldw, const float* __restrict__ b1, const float* __restrict__ addb,
                    const float* __restrict__ s, const float* __restrict__ sh,
                    const float* __restrict__ resid,
                    float* __restrict__ out, float* __restrict__ out2,
                    int Np, int Kd, int Od, int ldo, int ldo2, int act, int transOut) {
    const int BM = 128, BN = 128, BK = 32;
    int b  = blockIdx.z;
    int n0 = blockIdx.x * BM;
    int o0 = blockIdx.y * BN;
    const float* Xb = X + (size_t)b * Np * Kd;
    __shared__ float As[BK][BM + 4];
    __shared__ float Ws[BK][BN + 4];
    int tid = threadIdx.x;
    int tx = tid & 15, ty = tid >> 4;
    int lq = tid & 7, lr = tid >> 3;       // loader: 8 k-quads x 32 rows
    float acc[8][8];
    #pragma unroll
    for (int i = 0; i < 8; i++)
        #pragma unroll
        for (int j = 0; j < 8; j++) acc[i][j] = 0.f;
    bool vecOK = ((Kd & 31) == 0);
    for (int k0 = 0; k0 < Kd; k0 += BK) {
        int kbase = k0 + lq * 4;
        #pragma unroll
        for (int rr = 0; rr < 4; rr++) {
            int n = n0 + lr + rr * 32;
            float4 t = make_float4(0.f, 0.f, 0.f, 0.f);
            if (vecOK) {
                t = *(const float4*)&Xb[(size_t)n * Kd + kbase];
            } else {
                float tt[4] = {0.f, 0.f, 0.f, 0.f};
                #pragma unroll
                for (int u = 0; u < 4; u++)
                    if (kbase + u < Kd) tt[u] = Xb[(size_t)n * Kd + kbase + u];
                t = make_float4(tt[0], tt[1], tt[2], tt[3]);
            }
            int r = lr + rr * 32;
            As[lq * 4 + 0][r] = t.x; As[lq * 4 + 1][r] = t.y;
            As[lq * 4 + 2][r] = t.z; As[lq * 4 + 3][r] = t.w;
        }
        #pragma unroll
        for (int rr = 0; rr < 4; rr++) {
            int o = o0 + lr + rr * 32;
            float4 t = make_float4(0.f, 0.f, 0.f, 0.f);
            if (o < Od) {
                if (vecOK) {
                    t = *(const float4*)&W[(size_t)o * ldw + kbase];
                } else {
                    float tt[4] = {0.f, 0.f, 0.f, 0.f};
                    #pragma unroll
                    for (int u = 0; u < 4; u++)
                        if (kbase + u < Kd) tt[u] = W[(size_t)o * ldw + kbase + u];
                    t = make_float4(tt[0], tt[1], tt[2], tt[3]);
                }
            }
            int r = lr + rr * 32;
            Ws[lq * 4 + 0][r] = t.x; Ws[lq * 4 + 1][r] = t.y;
            Ws[lq * 4 + 2][r] = t.z; Ws[lq * 4 + 3][r] = t.w;
        }
        __syncthreads();
        #pragma unroll
        for (int kk = 0; kk < BK; kk++) {
            float a[8], w[8];
            *(float4*)&a[0] = *(const float4*)&As[kk][ty * 8];
            *(float4*)&a[4] = *(const float4*)&As[kk][ty * 8 + 4];
            *(float4*)&w[0] = *(const float4*)&Ws[kk][tx * 8];
            *(float4*)&w[4] = *(const float4*)&Ws[kk][tx * 8 + 4];
            #pragma unroll
            for (int i = 0; i < 8; i++)
                #pragma unroll
                for (int j = 0; j < 8; j++)
                    acc[i][j] = fmaf(a[i], w[j], acc[i][j]);
        }
        __syncthreads();
    }
    #pragma unroll
    for (int i = 0; i < 8; i++) {
        int n = n0 + ty * 8 + i;
        size_t base = (size_t)b * Np + n;
        #pragma unroll
        for (int j = 0; j < 8; j++) {
            int o = o0 + tx * 8 + j;
            if (o >= Od) continue;
            float y = acc[i][j];
            float pre = y + (b1 ? b1[o] : 0.f) + (addb ? addb[b * Od + o] : 0.f);
            float z = (s ? s[o] : 1.f) * pre + (sh ? sh[o] : 0.f);
            if (act == 1) z = fmaxf(z, 0.f);
            else if (act == 2) z = (z > 0.f) ? z : 0.2f * z;
            if (resid) z += resid[base * (size_t)ldo + o];
            if (transOut) out[((size_t)b * Od + o) * Np + n] = z;
            else          out[base * (size_t)ldo + o] = z;
            if (out2) out2[base * (size_t)ldo2 + o] = z;
        }
    }
}

// ---------------- attention scores + aggregation (no Wo) --------------------
// qkv layout: [p][384] with q at +0, k at +128, v at +256
__global__ void attn_agg_kernel(const float* __restrict__ qkv, const int* __restrict__ idx,
                                const float* __restrict__ in, const float* __restrict__ wpos,
                                float* __restrict__ agg) {
    int p = blockIdx.x;
    int b = p >> 12, n = p & (NPTS - 1);
    int tid = threadIdx.x;
    __shared__ float qs[CH], attn[KNN], slog[KNN], rel[KNN][3];
    __shared__ int sIdx[KNN];
    qs[tid] = qkv[(size_t)p * 384 + tid];
    if (tid < KNN) sIdx[tid] = idx[(size_t)p * KNN + tid];
    __syncthreads();
    const float* xb = in + (size_t)b * CIN * NPTS;
    int w = tid >> 5, lane = tid & 31;
    for (int kk = w; kk < KNN; kk += 4) {
        int m = sIdx[kk];
        const float* kr = qkv + ((size_t)b * NPTS + m) * 384 + CH;
        float d = 0.f;
        #pragma unroll
        for (int c = lane; c < CH; c += 32) d = fmaf(qs[c], kr[c], d);
        #pragma unroll
        for (int st = 16; st > 0; st >>= 1) d += __shfl_down_sync(0xffffffffu, d, st);
        if (lane == 0) slog[kk] = d * 0.08838834764831845f; // 1/sqrt(128)
        if (lane < 3)  rel[kk][lane] = xb[lane * NPTS + n] - xb[lane * NPTS + m];
    }
    __syncthreads();
    if (tid == 0) {
        float mx = slog[0];
        #pragma unroll
        for (int i = 1; i < KNN; i++) mx = fmaxf(mx, slog[i]);
        float sum = 0.f;
        #pragma unroll
        for (int i = 0; i < KNN; i++) { float e = expf(slog[i] - mx); attn[i] = e; sum += e; }
        float inv = 1.f / sum;
        #pragma unroll
        for (int i = 0; i < KNN; i++) attn[i] *= inv;
    }
    __syncthreads();
    float w0 = wpos[tid * 3 + 0], w1 = wpos[tid * 3 + 1], w2 = wpos[tid * 3 + 2];
    float acc = 0.f;
    #pragma unroll
    for (int kk = 0; kk < KNN; kk++) {
        int m = sIdx[kk];
        float vn = qkv[((size_t)b * NPTS + m) * 384 + 2 * CH + tid]
                 + w0 * rel[kk][0] + w1 * rel[kk][1] + w2 * rel[kk][2];
        acc = fmaf(attn[kk], vn, acc);
    }
    agg[(size_t)p * CH + tid] = acc;
}

// ---------------- global max/mean pool over n -------------------------------
__global__ void pool_kernel(const float* __restrict__ fuse, float* __restrict__ g) {
    int b = blockIdx.y;
    int ch = blockIdx.x * 32 + (threadIdx.x & 31);
    int r = threadIdx.x >> 5;
    float mx = -FLT_MAX, sm = 0.f;
    for (int n = r; n < NPTS; n += 8) {
        float v = fuse[((size_t)b * NPTS + n) * 1024 + ch];
        mx = fmaxf(mx, v); sm += v;
    }
    __shared__ float smx[256], ssm[256];
    smx[threadIdx.x] = mx; ssm[threadIdx.x] = sm;
    __syncthreads();
    for (int st = 128; st >= 32; st >>= 1) {
        if (threadIdx.x < st) {
            smx[threadIdx.x] = fmaxf(smx[threadIdx.x], smx[threadIdx.x + st]);
            ssm[threadIdx.x] += ssm[threadIdx.x + st];
        }
        __syncthreads();
    }
    if (r == 0) {
        g[b * 2048 + ch] = smx[threadIdx.x];
        g[b * 2048 + 1024 + ch] = ssm[threadIdx.x] * (1.f / 4096.f);
    }
}

// ------- fold global features into per-(b,o) cls1 bias ----------------------
__global__ void beff_kernel(const float* __restrict__ w1, const float* __restrict__ bias1,
                            const float* __restrict__ g, float* __restrict__ beff) {
    int o = blockIdx.x * blockDim.x + threadIdx.x;
    int b = blockIdx.y;
    if (o >= 512) return;
    const float* wr = w1 + (size_t)o * 3072 + 1024;
    const float* gb = g + b * 2048;
    float a0 = 0.f, a1 = 0.f, a2 = 0.f, a3 = 0.f;
    for (int j = 0; j < 2048; j += 4) {
        a0 = fmaf(wr[j + 0], gb[j + 0], a0);
        a1 = fmaf(wr[j + 1], gb[j + 1], a1);
        a2 = fmaf(wr[j + 2], gb[j + 2], a2);
        a3 = fmaf(wr[j + 3], gb[j + 3], a3);
    }
    beff[b * 512 + o] = bias1[o] + ((a0 + a1) + (a2 + a3));
}

// ---------------- launcher --------------------------------------------------
extern "C" void kernel_launch(void* const* d_in, const int* in_sizes, int n_in,
                              void* d_out, int out_size) {
    const float* in_inputs  = (const float*)d_in[0];
    const float* emb_w1     = (const float*)d_in[1];
    const float* emb_s1     = (const float*)d_in[2];
    const float* emb_b1     = (const float*)d_in[3];
    const float* emb_w2     = (const float*)d_in[4];
    const float* emb_s2     = (const float*)d_in[5];
    const float* emb_b2     = (const float*)d_in[6];
    const float* blk_wq     = (const float*)d_in[7];
    const float* blk_wk     = (const float*)d_in[8];
    const float* blk_wv     = (const float*)d_in[9];
    const float* blk_wpos   = (const float*)d_in[10];
    const float* blk_wo     = (const float*)d_in[11];
    const float* blk_s      = (const float*)d_in[12];
    const float* blk_b      = (const float*)d_in[13];
    const float* fuse_w     = (const float*)d_in[14];
    const float* fuse_s     = (const float*)d_in[15];
    const float* fuse_b     = (const float*)d_in[16];
    const float* cls_w1     = (const float*)d_in[17];
    const float* cls_bias1  = (const float*)d_in[18];
    const float* cls_s1     = (const float*)d_in[19];
    const float* cls_sh1    = (const float*)d_in[20];
    const float* cls_w2     = (const float*)d_in[21];
    const float* cls_bias2  = (const float*)d_in[22];
    const float* cls_s2     = (const float*)d_in[23];
    const float* cls_sh2    = (const float*)d_in[24];
    const float* cls_w3     = (const float*)d_in[25];
    const float* cls_bias3  = (const float*)d_in[26];

    float* pool = nullptr;
    cudaGetSymbolAddress((void**)&pool, g_pool);
    float* xin  = pool + OFF_XIN;
    int*   idx  = (int*)(pool + OFF_IDX);
    float* e1   = pool + OFF_E1;
    float* xcur = pool + OFF_XCUR;
    float* qkvb = pool + OFF_QKV;
    float* aggb = pool + OFF_AGG;
    float* xcat = pool + OFF_XCAT;
    float* fuse = pool + OFF_FUSE;
    float* g    = pool + OFF_G;
    float* beff = pool + OFF_BEFF;
    float* c1   = pool + OFF_C1;
    float* c2   = pool + OFF_C2;
    float* wpk  = pool + OFF_WPK;
    float* outp = (float*)d_out;

    const int P = BATCH * NPTS;

    tin_kernel<<<(P + 255) / 256, 256>>>(in_inputs, xin);
    pack_qkv_kernel<<<dim3(192, 3), 256>>>(blk_wq, blk_wk, blk_wv, wpk);
    knn_warp_kernel<<<P / 8, 256>>>(in_inputs, idx);

    // embedding: 9 -> 128 -> 128
    gemm128_kernel<<<dim3(32, 1, BATCH), 256>>>(xin, emb_w1, CIN, nullptr, nullptr,
        emb_s1, emb_b1, nullptr, e1, nullptr, NPTS, CIN, CH, CH, 0, 1, 0);
    gemm128_kernel<<<dim3(32, 1, BATCH), 256>>>(e1, emb_w2, CH, nullptr, nullptr,
        emb_s2, emb_b2, nullptr, xcur, nullptr, NPTS, CH, CH, CH, 0, 1, 0);

    // attention blocks
    for (int i = 0; i < 3; i++) {
        // fused qkv projection: [p][384]
        gemm128_kernel<<<dim3(32, 3, BATCH), 256>>>(xcur, wpk + (size_t)i * 384 * CH, CH,
            nullptr, nullptr, nullptr, nullptr, nullptr, qkvb, nullptr,
            NPTS, CH, 384, 384, 0, 0, 0);
        attn_agg_kernel<<<P, CH>>>(qkvb, idx, in_inputs,
                                   blk_wpos + (size_t)i * CH * 3, aggb);
        // Wo + scale/bias + relu + residual, dual write (xcur, xcat slice)
        gemm128_kernel<<<dim3(32, 1, BATCH), 256>>>(aggb, blk_wo + (size_t)i * CH * CH, CH,
            nullptr, nullptr, blk_s + (size_t)i * CH, blk_b + (size_t)i * CH,
            xcur, xcur, xcat + i * CH, NPTS, CH, CH, CH, 3 * CH, 1, 0);
    }

    // fuse 384 -> 1024 (leaky 0.2)
    gemm128_kernel<<<dim3(32, 8, BATCH), 256>>>(xcat, fuse_w, 3 * CH, nullptr, nullptr,
        fuse_s, fuse_b, nullptr, fuse, nullptr, NPTS, 3 * CH, 1024, 1024, 0, 2, 0);

    // global pool + fold into cls1 bias
    pool_kernel<<<dim3(32, BATCH), 256>>>(fuse, g);
    beff_kernel<<<dim3(2, BATCH), 256>>>(cls_w1, cls_bias1, g, beff);

    // classifier
    gemm128_kernel<<<dim3(32, 4, BATCH), 256>>>(fuse, cls_w1, 3072, nullptr, beff,
        cls_s1, cls_sh1, nullptr, c1, nullptr, NPTS, 1024, 512, 512, 0, 1, 0);
    gemm128_kernel<<<dim3(32, 2, BATCH), 256>>>(c1, cls_w2, 512, cls_bias2, nullptr,
        cls_s2, cls_sh2, nullptr, c2, nullptr, NPTS, 512, 256, 256, 0, 1, 0);
    gemm128_kernel<<<dim3(32, 1, BATCH), 256>>>(c2, cls_w3, 256, cls_bias3, nullptr,
        nullptr, nullptr, nullptr, outp, nullptr, NPTS, 256, NCLS, NCLS, 0, 0, 1);
}